// round 1
// baseline (speedup 1.0000x reference)
#include <cuda_runtime.h>
#include <cstdint>
#include <math.h>

#define NN 4096
#define TPB 256
#define EPT 16            // NN / TPB
#define HSZ 4096
#define HMASK 4095
#define KMAX 128
#define KNEI 5

// device scratch (static allocation is allowed; no cudaMalloc anywhere)
__device__ int      g_count;
__device__ unsigned g_cells[HSZ];
__device__ float    g_delta[HSZ];

static __device__ __forceinline__ unsigned hslot(unsigned key) {
    return (key * 2654435761u) >> 20;   // top 12 bits -> [0,4095]
}

static __device__ __forceinline__ float hash_get(const unsigned* HK, const float* HV, unsigned key) {
    unsigned s = hslot(key);
    while (true) {
        unsigned k = HK[s];
        if (k == key) return HV[s];
        if (k == 0u)  return 0.0f;
        s = (s + 1u) & HMASK;
    }
}

static __device__ __forceinline__ void hash_add(unsigned* HK, float* HV, unsigned key, float dv) {
    unsigned s = hslot(key);
    while (true) {
        unsigned k = HK[s];
        if (k == 0u) k = atomicCAS(&HK[s], 0u, key);
        if (k == 0u || k == key) { atomicAdd(&HV[s], dv); return; }
        s = (s + 1u) & HMASK;
    }
}

static __device__ __forceinline__ void cp_row(float* dst, const float* src, int tid) {
    unsigned sa = (unsigned)__cvta_generic_to_shared(dst + tid * EPT);
    const float* g = src + tid * EPT;
#pragma unroll
    for (int j = 0; j < EPT / 4; j++) {
        asm volatile("cp.async.cg.shared.global [%0], [%1], 16;\n"
                     :: "r"(sa + j * 16), "l"(g + j * 4));
    }
}

// ---------------------------------------------------------------------------
// K1: s = sigmoid(W @ (0.95*s) + 0.05*noise). Fast path when s == 0 (detected
// at runtime, so the kernel stays fully general): skips the 67MB W read.
// ---------------------------------------------------------------------------
__global__ void k_state(const float* __restrict__ W, const float* __restrict__ s,
                        const float* __restrict__ noise, float* __restrict__ out) {
    __shared__ float sdec[NN];
    __shared__ float red[4];
    int any = 0;
    for (int i = threadIdx.x; i < NN; i += blockDim.x) {
        float v = s[i];
        sdec[i] = v * 0.95f;
        any |= (v != 0.0f);
    }
    if (__syncthreads_or(any) == 0) {
        int i = blockIdx.x * blockDim.x + threadIdx.x;
        if (i < NN) out[i] = 1.0f / (1.0f + expf(-0.05f * noise[i]));
        return;
    }
    // general matvec path (not exercised when s == 0, kept for correctness)
    int rows = NN / gridDim.x;
    for (int r = blockIdx.x * rows; r < (blockIdx.x + 1) * rows; r++) {
        const float* row = W + (size_t)r * NN;
        float acc = 0.0f;
        for (int j = threadIdx.x; j < NN; j += blockDim.x) acc += row[j] * sdec[j];
#pragma unroll
        for (int o = 16; o; o >>= 1) acc += __shfl_xor_sync(~0u, acc, o);
        if ((threadIdx.x & 31) == 0) red[threadIdx.x >> 5] = acc;
        __syncthreads();
        if (threadIdx.x == 0) {
            float a = red[0] + red[1] + red[2] + red[3];
            out[r] = 1.0f / (1.0f + expf(-(a + 0.05f * noise[r])));
        }
        __syncthreads();
    }
}

// ---------------------------------------------------------------------------
// K2: block 0 runs the sequential spark scan (delta-hash overlay on W);
//     blocks 1..G-1 concurrently stream W -> out with decay+clip.
// ---------------------------------------------------------------------------
__global__ void k_main(const float* __restrict__ W, const float* __restrict__ u_in,
                       const int* __restrict__ pos_in, const float* __restrict__ en_in,
                       const int* __restrict__ age_in, float* __restrict__ out, int K) {
    if (blockIdx.x != 0) {
        // ---- decay + clip copy of W into out[NN .. NN+NN*NN) ----
        const int nblk = gridDim.x - 1;
        const size_t nv = (size_t)NN * NN / 4;
        float4* dst = (float4*)(out + NN);
        const float4* src = (const float4*)W;
        size_t stride = (size_t)nblk * blockDim.x;
#pragma unroll 4
        for (size_t i = (size_t)(blockIdx.x - 1) * blockDim.x + threadIdx.x; i < nv; i += stride) {
            float4 v = src[i];
            v.x = fminf(fmaxf(v.x * 0.999f, -2.0f), 2.0f);
            v.y = fminf(fmaxf(v.y * 0.999f, -2.0f), 2.0f);
            v.z = fminf(fmaxf(v.z * 0.999f, -2.0f), 2.0f);
            v.w = fminf(fmaxf(v.w * 0.999f, -2.0f), 2.0f);
            dst[i] = v;
        }
        return;
    }

    // ---- spark block ----
    extern __shared__ char sm[];
    float*    s_sh = (float*)sm;            // NN
    float*    bufA = s_sh + NN;             // NN
    float*    bufB = bufA + NN;             // NN
    unsigned* HK   = (unsigned*)(bufB + NN);// HSZ
    float*    HV   = (float*)(HK + HSZ);    // HSZ

    __shared__ int   prevs[KMAX];
    __shared__ float en[KMAX];
    __shared__ int   ag[KMAX];
    __shared__ int   poso[KMAX];
    __shared__ float uarr[KMAX];
    __shared__ long long wsum[TPB / 32];
    __shared__ int  wcnt[TPB / 32];
    __shared__ unsigned long long wmax[KNEI][TPB / 32];
    __shared__ int   sh_eflag;
    __shared__ float sh_dset;
    __shared__ int   sh_cnt;

    const int tid = threadIdx.x, lane = tid & 31, wid = tid >> 5;

    for (int i = tid; i < NN; i += TPB) s_sh[i] = out[i];          // s from k_state
    for (int i = tid; i < HSZ; i += TPB) { HK[i] = 0u; HV[i] = 0.0f; }
    if (tid < K) {
        prevs[tid] = pos_in[tid];
        en[tid]    = en_in[tid];
        ag[tid]    = age_in[tid];
        uarr[tid]  = u_in[tid];
    }
    if (tid == 0) sh_cnt = 0;
    __syncthreads();
    // force young sparks (uses INPUT ages)
    if (tid < K && ag[tid] < 5) s_sh[prevs[tid]] = 1.0f;
    __syncthreads();

    // prefetch row 0
    cp_row(bufA, W + (size_t)prevs[0] * NN, tid);
    asm volatile("cp.async.commit_group;\n");

    for (int it = 0; it < K; it++) {
        float* cur = (it & 1) ? bufB : bufA;
        float* nb  = (it & 1) ? bufA : bufB;
        const int prev = prevs[it];

        asm volatile("cp.async.wait_group 0;\n");
        __syncthreads();

        // patch prefetched base row with accumulated deltas
        for (int slot = tid; slot < HSZ; slot += TPB) {
            unsigned k = HK[slot];
            if (k) {
                unsigned kk = k - 1u;
                if ((int)(kk >> 12) == prev) cur[kk & 4095u] += HV[slot];
            }
        }
        __syncthreads();

        if (it + 1 < K) {
            cp_row(nb, W + (size_t)prevs[it + 1] * NN, tid);
            asm volatile("cp.async.commit_group;\n");
        }

        // ---- exact inverse-CDF sample via int64 fixed-point (2^-40 quantum) ----
        long long lp[EPT];
        long long run = 0;
#pragma unroll
        for (int j = 0; j < EPT; j++) {
            float v = cur[tid * EPT + j];
            float w = fmaxf(v, 0.0f) + 1e-6f;
            long long q = (long long)(w * 1099511627776.0f);  // * 2^40 (exact scale)
            run += q;
            lp[j] = run;
        }
        long long inc = run;
#pragma unroll
        for (int o = 1; o < 32; o <<= 1) {
            long long t = __shfl_up_sync(~0u, inc, o);
            if (lane >= o) inc += t;
        }
        if (lane == 31) wsum[wid] = inc;
        __syncthreads();
        long long wbase = 0, total = 0;
#pragma unroll
        for (int w2 = 0; w2 < TPB / 32; w2++) {
            long long t = wsum[w2];
            total += t;
            if (w2 < wid) wbase += t;
        }
        const long long base = wbase + inc - run;   // exclusive prefix for this thread
        const long long target = (long long)((double)uarr[it] * (double)total);
        int c = 0;
#pragma unroll
        for (int j = 0; j < EPT; j++) c += (base + lp[j] <= target);
        c = (int)__reduce_add_sync(~0u, (unsigned)c);
        if (lane == 0) wcnt[wid] = c;
        __syncthreads();
        int count = 0;
#pragma unroll
        for (int w2 = 0; w2 < TPB / 32; w2++) count += wcnt[w2];
        const int nxt = min(count, NN - 1);

        // issue the edge-cell base load early (latency hidden behind top5 build)
        float basenp = 0.0f;
        if (tid == 0) basenp = W[(size_t)nxt * NN + prev];

        // per-thread sorted top-5 of relu(row), packed for exact lax.top_k tiebreak
        unsigned long long L[KNEI] = {0, 0, 0, 0, 0};
#pragma unroll
        for (int j = 0; j < EPT; j++) {
            int idx = tid * EPT + j;
            float v = fmaxf(cur[idx], 0.0f);
            unsigned long long p = ((unsigned long long)__float_as_uint(v) << 12) | (unsigned)(4095 - idx);
            if (p > L[KNEI - 1]) {
                int q = KNEI - 1;
                while (q > 0 && L[q - 1] < p) { L[q] = L[q - 1]; q--; }
                L[q] = p;
            }
        }

        // edge learning: W[nxt,prev] = 0.95*W[nxt,prev] + 0.05*s[prev]  (as a delta)
        if (tid == 0) {
            unsigned key = (unsigned)nxt * 4096u + (unsigned)prev + 1u;
            float curv = basenp + hash_get(HK, HV, key);
            float newv = curv * 0.95f + s_sh[prev] * 0.05f;
            float ds = newv - curv;
            hash_add(HK, HV, key, ds);
            sh_eflag = (nxt == prev);
            sh_dset = ds;
        }
        __syncthreads();
        if (sh_eflag) {      // rare: edge update landed in row prev -> repatch & rebuild
            if (tid == (prev >> 4)) {
                cur[prev] += sh_dset;
                L[0] = L[1] = L[2] = L[3] = L[4] = 0;
                for (int j = 0; j < EPT; j++) {
                    int idx = tid * EPT + j;
                    float v = fmaxf(cur[idx], 0.0f);
                    unsigned long long p = ((unsigned long long)__float_as_uint(v) << 12) | (unsigned)(4095 - idx);
                    if (p > L[KNEI - 1]) {
                        int q = KNEI - 1;
                        while (q > 0 && L[q - 1] < p) { L[q] = L[q - 1]; q--; }
                        L[q] = p;
                    }
                }
            }
            __syncthreads();
        }

        // block top-5 via 5 cheap rounds over per-thread sorted lists
        int top[KNEI];
        int p = 0;
#pragma unroll
        for (int r = 0; r < KNEI; r++) {
            unsigned long long m = (p < KNEI) ? L[p] : 0ull;
            unsigned long long cand = m;
#pragma unroll
            for (int o = 16; o; o >>= 1) {
                unsigned long long t = __shfl_xor_sync(~0u, m, o);
                m = (t > m) ? t : m;
            }
            if (lane == 0) wmax[r][wid] = m;
            __syncthreads();
            unsigned long long gm = 0;
#pragma unroll
            for (int w2 = 0; w2 < TPB / 32; w2++) {
                unsigned long long t = wmax[r][w2];
                gm = (t > gm) ? t : gm;
            }
            if (p < KNEI && cand == gm && L[p] == gm) p++;
            top[r] = 4095 - (int)(gm & 0xFFFull);
        }

        // ripple adds (35 independent delta adds; order-free, atomics)
        if (tid < 35) {
            int rr, cc; float dv;
            if (tid < 5)       { rr = prev;          cc = top[tid];      dv = 0.01f;  }
            else if (tid < 10) { rr = top[tid - 5];  cc = prev;          dv = 0.005f; }
            else { int i5 = (tid - 10) / 5, j5 = (tid - 10) % 5;
                   rr = top[i5]; cc = top[j5]; dv = 0.003f; }
            hash_add(HK, HV, (unsigned)rr * 4096u + (unsigned)cc + 1u, dv);
        }

        // bookkeeping
        if (tid == 0) {
            float e = en[it] * 0.98f;
            s_sh[nxt] = e;                 // deposit BEFORE respawn check (as in ref)
            int a = ag[it] + 1;
            int po = nxt;
            if (e < 0.05f) { po = it; e = 1.0f; a = 0; }
            poso[it] = po; en[it] = e; ag[it] = a;
        }
        __syncthreads();
    }

    // ---- outputs ----
    for (int i = tid; i < NN; i += TPB) out[i] = s_sh[i];
    const size_t OFF = (size_t)NN + (size_t)NN * NN;
    if (tid < K) {
        out[OFF + tid]          = (float)poso[tid];
        out[OFF + K + tid]      = en[tid];
        out[OFF + 2 * K + tid]  = (float)ag[tid];
    }
    // dump delta hash for the fixup kernel
    for (int slot = tid; slot < HSZ; slot += TPB) {
        unsigned k = HK[slot];
        if (k) {
            int i = atomicAdd(&sh_cnt, 1);
            g_cells[i] = k - 1u;
            g_delta[i] = HV[slot];
        }
    }
    __syncthreads();
    if (tid == 0) g_count = sh_cnt;
}

// ---------------------------------------------------------------------------
// K3: overwrite the (<=1152) spark-edited W cells with (base+delta)*0.999, clipped
// ---------------------------------------------------------------------------
__global__ void k_fix(const float* __restrict__ W, float* __restrict__ out) {
    int n = g_count;
    for (int i = blockIdx.x * blockDim.x + threadIdx.x; i < n; i += gridDim.x * blockDim.x) {
        unsigned cell = g_cells[i];
        float v = (W[cell] + g_delta[i]) * 0.999f;
        v = fminf(fmaxf(v, -2.0f), 2.0f);
        out[(size_t)NN + cell] = v;
    }
}

extern "C" void kernel_launch(void* const* d_in, const int* in_sizes, int n_in,
                              void* d_out, int out_size) {
    const float* W     = (const float*)d_in[0];
    const float* s     = (const float*)d_in[1];
    const float* noise = (const float*)d_in[2];
    const float* en    = (const float*)d_in[3];
    const float* u     = (const float*)d_in[4];
    const int*   pos   = (const int*)d_in[5];
    const int*   age   = (const int*)d_in[6];
    float* out = (float*)d_out;
    int K = in_sizes[3];
    if (K > KMAX) K = KMAX;

    const int smem = (3 * NN) * 4 + HSZ * 4 + HSZ * 4;   // 80 KB
    cudaFuncSetAttribute(k_main, cudaFuncAttributeMaxDynamicSharedMemorySize, smem);

    k_state<<<32, 128>>>(W, s, noise, out);
    k_main<<<149, TPB, smem>>>(W, u, pos, en, age, out, K);
    k_fix<<<16, 256>>>(W, out);
}